// round 11
// baseline (speedup 1.0000x reference)
#include <cuda_runtime.h>
#include <cuda_fp16.h>
#include <cstdint>

#define FIELD 39
#define DIM   64
#define NTHR  512
#define BATCH 2048

// SMEM layout (bytes)
#define HP0  40
#define HPH0 264
#define SO_X0T 0                       // fp32 x0T [d][i], stride 40
#define SO_X0H 10240                   // fp16 x0 hi(6144)+lo(6144) [i<48][d]
#define SO_H0T 22528                   // fp32 h0T [d][j], stride 264 (67584 B)
#define SO_H1H 90112                   // fp16 h1 hi(16K)+lo(16K) [j<128][d]
#define SO_B   122880                  // B dbuf 2x16K; later g32 / scratch
#define SO_A   155648                  // A dbuf / scratch / GEMV ring (64K)
#define SMEM_BYTES 221184

// Prepped W^T fp16 tile images (swizzle baked).
__device__ __align__(16) unsigned short gA0[48u  * 8192];  // 128x64 tiles
__device__ __align__(16) unsigned short gA1[156u * 8192];  // 128x64 tiles
__device__ __align__(16) unsigned short gA2[78u  * 4096];  // 64x64 tiles

__device__ __forceinline__ uint32_t swz(uint32_t off) {
    return off ^ ((off >> 3) & 0x70);
}
__device__ __forceinline__ void ldm4(uint32_t a, uint32_t r[4]) {
    asm volatile("ldmatrix.sync.aligned.m8n8.x4.shared.b16 {%0,%1,%2,%3}, [%4];"
                 : "=r"(r[0]), "=r"(r[1]), "=r"(r[2]), "=r"(r[3]) : "r"(a));
}
__device__ __forceinline__ void mmah(float c[4], const uint32_t a[4],
                                     uint32_t b0, uint32_t b1) {
    asm volatile("mma.sync.aligned.m16n8k16.row.col.f32.f16.f16.f32 "
                 "{%0,%1,%2,%3},{%4,%5,%6,%7},{%8,%9},{%0,%1,%2,%3};"
                 : "+f"(c[0]), "+f"(c[1]), "+f"(c[2]), "+f"(c[3])
                 : "r"(a[0]), "r"(a[1]), "r"(a[2]), "r"(a[3]), "r"(b0), "r"(b1));
}
__device__ __forceinline__ void cpasync16(uint32_t s, const void* g) {
    asm volatile("cp.async.cg.shared.global [%0], [%1], 16;" :: "r"(s), "l"(g));
}
#define CP_COMMIT() asm volatile("cp.async.commit_group;")
#define CP_WAIT0()  asm volatile("cp.async.wait_group 0;")
#define CP_WAIT1()  asm volatile("cp.async.wait_group 1;")

__device__ __forceinline__ unsigned short hbits(__half h) {
    return *(unsigned short*)&h;
}
__device__ __forceinline__ uint32_t pack2h(float a, float b) {
    return (uint32_t)hbits(__float2half_rn(a)) |
           ((uint32_t)hbits(__float2half_rn(b)) << 16);
}
// packed split: hi = f16x2(a,b), lo = f16x2 of residuals
__device__ __forceinline__ uint32_t split2h2(float a, float b, uint32_t& lo) {
    const __half2 h = __floats2half2_rn(a, b);
    const float2 hf = __half22float2(h);
    const __half2 l = __floats2half2_rn(a - hf.x, b - hf.y);
    lo = *(const uint32_t*)&l;
    return *(const uint32_t*)&h;
}

// ---- prep: W -> swizzle-baked fp16 W^T tile images ----
__global__ void prep_kernel(const float* __restrict__ W0,
                            const float* __restrict__ W1,
                            const float* __restrict__ W2) {
    const int tile = blockIdx.x;
    const float* W; unsigned short* A; int K, Lv, kt, mt, rows;
    if (tile < 48)       { kt = tile >> 1; mt = tile & 1; W = W0; K = 1521; Lv = 256;
                           rows = 128; A = gA0 + (size_t)tile * 8192; }
    else if (tile < 204) { int u = tile - 48;  kt = u; mt = 0; W = W1; K = 9984; Lv = 128;
                           rows = 128; A = gA1 + (size_t)u * 8192; }
    else                 { int u = tile - 204; kt = u; mt = 0; W = W2; K = 4992; Lv = 64;
                           rows = 64;  A = gA2 + (size_t)u * 4096; }
    for (int it = threadIdx.x; it < rows * 8; it += blockDim.x) {
        const int row = it % rows, cg = it / rows;
        const int l = mt * 128 + row;
        uint32_t hw[4];
        #pragma unroll
        for (int p = 0; p < 4; p++) {
            float v0 = 0.f, v1 = 0.f;
            const int k0 = kt * 64 + cg * 8 + 2 * p;
            if (l < Lv) {
                if (k0     < K) v0 = W[(size_t)k0 * Lv + l];
                if (k0 + 1 < K) v1 = W[(size_t)(k0 + 1) * Lv + l];
            }
            hw[p] = pack2h(v0, v1);
        }
        const uint32_t sw = swz((uint32_t)(row * 128 + cg * 16));
        *(uint4*)((char*)A + sw) = make_uint4(hw[0], hw[1], hw[2], hw[3]);
    }
}

// ---- build one 64-k B chunk: B[d][k] = x0[i,d]*h[j,d], fp16 hi/lo ----
template<int FK, int HPREV>
__device__ __forceinline__ void build_b(char* smem, int t, uint32_t bst,
                                        const float* __restrict__ hprevT) {
    const int tid = threadIdx.x;
    const float* x0T = (const float*)(smem + SO_X0T);
    const int d = tid >> 3, g = tid & 7;
    const int kb = t * 64 + g * 8;
    float v[8];
    if (FK == FIELD) {
        #pragma unroll
        for (int e = 0; e < 8; e++) {
            const int k = kb + e, i = k / FIELD, j = k - i * FIELD;
            v[e] = x0T[d * HP0 + i] * x0T[d * HP0 + j];
        }
    } else {
        const int i = kb / FK, j0 = kb % FK;
        const float xv = x0T[d * HP0 + i];
        const float4 a = *(const float4*)(hprevT + d * HPREV + j0);
        const float4 b = *(const float4*)(hprevT + d * HPREV + j0 + 4);
        v[0]=xv*a.x; v[1]=xv*a.y; v[2]=xv*a.z; v[3]=xv*a.w;
        v[4]=xv*b.x; v[5]=xv*b.y; v[6]=xv*b.z; v[7]=xv*b.w;
    }
    uint32_t hw[4], lw[4];
    #pragma unroll
    for (int p = 0; p < 4; p++) hw[p] = split2h2(v[2*p], v[2*p+1], lw[p]);
    const uint32_t sw = swz((uint32_t)(d * 128 + g * 16));
    char* bb = smem + SO_B + bst;
    *(uint4*)(bb + sw)        = make_uint4(hw[0], hw[1], hw[2], hw[3]);
    *(uint4*)(bb + 8192 + sw) = make_uint4(lw[0], lw[1], lw[2], lw[3]);
}

// ---- one 64-k chunk: warp computes a 64x32 tile over KKS kk's ----
// swz(row*128 + ch) = row*128 + (ch ^ ((row&7)<<4)) for ch < 128.
template<int L, int KKS>
__device__ __forceinline__ void chunk_mma64(uint32_t su, uint32_t ast,
                                            uint32_t bst, int lrow, int dcol,
                                            int kk0, float acc[4][4][4]) {
    const int lane = threadIdx.x & 31;
    const uint32_t hi16 = (uint32_t)((lane >> 4) * 16);
    uint32_t abase[4], amask[4], bbase[2], bmask[2];
    #pragma unroll
    for (int mi = 0; mi < 4; mi++) {
        const int l = lrow + mi * 16 + (lane & 15);
        const int mt = (L == 256) ? (l >> 7) : 0;
        const int r  = (L == 256) ? (l & 127) : l;
        abase[mi] = su + SO_A + ast + (uint32_t)mt * 16384u + (uint32_t)r * 128u;
        amask[mi] = (uint32_t)((r & 7) << 4);
    }
    #pragma unroll
    for (int nb = 0; nb < 2; nb++) {
        const int d = dcol + nb * 16 + (lane & 15);
        bbase[nb] = su + SO_B + bst + (uint32_t)d * 128u;
        bmask[nb] = (uint32_t)((d & 7) << 4);
    }
    #pragma unroll
    for (int u = 0; u < KKS; u++) {
        const int kk = kk0 + u;
        const uint32_t ch = (uint32_t)(kk * 32) + hi16;
        uint32_t ah[4][4], bh[2][4], bl[2][4];
        #pragma unroll
        for (int nb = 0; nb < 2; nb++) {
            const uint32_t ba = bbase[nb] + (ch ^ bmask[nb]);
            ldm4(ba, bh[nb]);
            ldm4(ba + 8192u, bl[nb]);
        }
        #pragma unroll
        for (int mi = 0; mi < 4; mi++)
            ldm4(abase[mi] + (ch ^ amask[mi]), ah[mi]);
        #pragma unroll
        for (int mi = 0; mi < 4; mi++)
            #pragma unroll
            for (int j = 0; j < 4; j++) {
                const int nb = j >> 1, q = j & 1;
                mmah(acc[mi][j], ah[mi], bh[nb][q], bh[nb][q + 2]);
                mmah(acc[mi][j], ah[mi], bl[nb][q], bl[nb][q + 2]);
            }
    }
}

// ---- one CIN layer. EPI=0: fp32 [d][l] store. EPI=1: fp16 h1 + rowsums ----
template<int L, int FK, int NKT, int HPREV, int HPOUT, int EPI>
__device__ void run_layer(char* smem, uint32_t su, const unsigned short* gA,
                          const float* __restrict__ hprevT, float* houtT,
                          const float* __restrict__ biasg, float* outAcc) {
    const int tid = threadIdx.x, wid = tid >> 5, lane = tid & 31;
    constexpr int NMT = L / 64;                 // 4 / 2
    constexpr int NTILES = NMT * 2;             // 8 / 4
    constexpr int S = 16 / NTILES;              // 2 / 4
    constexpr int KKS = 4 / S;                  // 2 / 1
    constexpr uint32_t ASTB = (uint32_t)L * 128u;
    const int tile = wid % NTILES, slice = wid / NTILES;
    const int lrow = (tile % NMT) * 64, dcol = (tile / NMT) * 32;
    const int kk0 = slice * KKS;

    float acc[4][4][4];
    #pragma unroll
    for (int mi = 0; mi < 4; mi++)
        #pragma unroll
        for (int j = 0; j < 4; j++)
            #pragma unroll
            for (int q = 0; q < 4; q++) acc[mi][j][q] = 0.f;

    auto stage_a = [&](int t) {
        const uint32_t dst = su + SO_A + (uint32_t)(t & 1) * 32768u;
        const char* src = (const char*)gA + (size_t)t * ASTB;
        constexpr int N16 = (int)(ASTB / 16);
        for (int idx = tid; idx < N16; idx += NTHR)
            cpasync16(dst + (uint32_t)idx * 16, src + idx * 16);
        CP_COMMIT();
    };

    stage_a(0);
    build_b<FK, HPREV>(smem, 0, 0, hprevT);
    CP_WAIT0();
    __syncthreads();

    for (int t = 0; t < NKT; t++) {
        const bool more = (t + 1 < NKT);
        if (more) stage_a(t + 1);
        chunk_mma64<L, KKS>(su, (uint32_t)(t & 1) * 32768u,
                            (uint32_t)(t & 1) * 16384u, lrow, dcol, kk0, acc);
        if (more) build_b<FK, HPREV>(smem, t + 1, ((t + 1) & 1) * 16384u, hprevT);
        CP_WAIT0();
        __syncthreads();
    }

    // ---- k-slice reduction through B+A scratch (both dead now) ----
    {
        if (slice != 0) {
            float4* dst = (float4*)(smem + SO_B +
                (size_t)(((slice - 1) * NTILES + tile) * 8192 + lane * 256));
            #pragma unroll
            for (int mi = 0; mi < 4; mi++)
                #pragma unroll
                for (int j = 0; j < 4; j++)
                    dst[mi * 4 + j] = *(float4*)acc[mi][j];
        }
        __syncthreads();
        if (slice == 0) {
            #pragma unroll
            for (int s = 1; s < S; s++) {
                const float4* src = (const float4*)(smem + SO_B +
                    (size_t)(((s - 1) * NTILES + tile) * 8192 + lane * 256));
                #pragma unroll
                for (int mi = 0; mi < 4; mi++)
                    #pragma unroll
                    for (int j = 0; j < 4; j++) {
                        const float4 v = src[mi * 4 + j];
                        acc[mi][j][0] += v.x; acc[mi][j][1] += v.y;
                        acc[mi][j][2] += v.z; acc[mi][j][3] += v.w;
                    }
            }
        }
    }

    if (slice == 0) {
        const int g = lane >> 2, t4 = lane & 3;
        if (EPI == 0) {
            #pragma unroll
            for (int mi = 0; mi < 4; mi++) {
                const int la = lrow + mi * 16 + g;
                const float b0 = biasg[la], b1 = biasg[la + 8];
                #pragma unroll
                for (int j = 0; j < 4; j++) {
                    const int db = dcol + (j >> 1) * 16 + (j & 1) * 8 + 2 * t4;
                    houtT[db * HPOUT + la]           = acc[mi][j][0] + b0;
                    houtT[(db + 1) * HPOUT + la]     = acc[mi][j][1] + b0;
                    houtT[db * HPOUT + la + 8]       = acc[mi][j][2] + b1;
                    houtT[(db + 1) * HPOUT + la + 8] = acc[mi][j][3] + b1;
                }
            }
        } else {
            #pragma unroll
            for (int mi = 0; mi < 4; mi++) {
                const int la = lrow + mi * 16 + g;
                const float b0 = biasg[la], b1 = biasg[la + 8];
                float s0 = 0.f, s1 = 0.f;
                #pragma unroll
                for (int j = 0; j < 4; j++) {
                    const int db = dcol + (j >> 1) * 16 + (j & 1) * 8 + 2 * t4;
                    uint32_t lo, hi;
                    hi = split2h2(acc[mi][j][0] + b0, acc[mi][j][1] + b0, lo);
                    *(uint32_t*)(smem + SO_H1H + swz((uint32_t)(la * 128 + db * 2))) = hi;
                    *(uint32_t*)(smem + SO_H1H + 16384u + swz((uint32_t)(la * 128 + db * 2))) = lo;
                    hi = split2h2(acc[mi][j][2] + b1, acc[mi][j][3] + b1, lo);
                    *(uint32_t*)(smem + SO_H1H + swz((uint32_t)((la + 8) * 128 + db * 2))) = hi;
                    *(uint32_t*)(smem + SO_H1H + 16384u + swz((uint32_t)((la + 8) * 128 + db * 2))) = lo;
                    s0 += acc[mi][j][0] + acc[mi][j][1];
                    s1 += acc[mi][j][2] + acc[mi][j][3];
                }
                s0 += __shfl_xor_sync(0xffffffffu, s0, 1);
                s0 += __shfl_xor_sync(0xffffffffu, s0, 2);
                s1 += __shfl_xor_sync(0xffffffffu, s1, 1);
                s1 += __shfl_xor_sync(0xffffffffu, s1, 2);
                if (t4 == 0) {
                    outAcc[(dcol >> 5) * 128 + la]     = s0;
                    outAcc[(dcol >> 5) * 128 + la + 8] = s1;
                }
            }
        }
    }
    __syncthreads();
}

__global__ void __launch_bounds__(NTHR, 1)
cin_mma_kernel(const void* __restrict__ feat_ids_raw,
               const float* __restrict__ emb,
               const float* __restrict__ b0g, const float* __restrict__ b1g,
               const float* __restrict__ b2g, float* __restrict__ out) {
    extern __shared__ char smem[];
    const uint32_t su = (uint32_t)__cvta_generic_to_shared(smem);
    const int b = blockIdx.x, tid = threadIdx.x, wid = tid >> 5, lane = tid & 31;
    float* x0T = (float*)(smem + SO_X0T);
    float* h0T = (float*)(smem + SO_H0T);
    __shared__ long long sids[FIELD];
    __shared__ int is64flag;
    __shared__ float outAcc[2 * 128];
    __shared__ float gpart[256];

    if (tid == 0) {
        const unsigned int* w = (const unsigned int*)feat_ids_raw;
        int f = 1;
        #pragma unroll
        for (int t = 0; t < 32; t++) if (w[2*t+1] != 0u) { f = 0; break; }
        is64flag = f;
    }
    __syncthreads();
    if (tid < FIELD) {
        sids[tid] = is64flag
            ? ((const long long*)feat_ids_raw)[(size_t)b * FIELD + tid]
            : (long long)((const int*)feat_ids_raw)[(size_t)b * FIELD + tid];
    }
    __syncthreads();
    for (int t = tid; t < FIELD * DIM; t += NTHR) {
        const int i = t >> 6, d = t & 63;
        x0T[d * HP0 + i] = emb[(size_t)sids[i] * DIM + d];
    }
    if (tid < 64) x0T[tid * HP0 + FIELD] = 0.f;   // zero pad col (K padding)
    __syncthreads();
    // x0h: fp16 hi/lo [i<48][d] swizzled rows (pairs of adjacent d)
    for (int e = tid; e < 48 * 32; e += NTHR) {
        const int i = e >> 5, dp = (e & 31) * 2;
        float v0 = 0.f, v1 = 0.f;
        if (i < FIELD) { v0 = x0T[dp * HP0 + i]; v1 = x0T[(dp + 1) * HP0 + i]; }
        uint32_t lo;
        const uint32_t hi = split2h2(v0, v1, lo);
        const uint32_t off = swz((uint32_t)(i * 128 + dp * 2));
        *(uint32_t*)(smem + SO_X0H + off) = hi;
        *(uint32_t*)(smem + SO_X0H + 6144u + off) = lo;
    }
    __syncthreads();

    run_layer<256,  39,  24, HP0,  HPH0, 0>(smem, su, gA0, x0T, h0T, b0g, outAcc);
    run_layer<128, 256, 156, HPH0,    0, 1>(smem, su, gA1, h0T, (float*)0, b1g, outAcc);

    float* outb = out + (size_t)b * 448;
    if (tid < 128)
        outb[256 + tid] = outAcc[tid] + outAcc[128 + tid] + 64.f * b1g[tid];

    // ---- G = H1 (128xK64) x X0^T (48) : 3-product fp16 GEMM ----
    float* g32 = (float*)(smem + SO_B);
    if (wid < 8) {
        const int jb = wid * 16;
        float ga[6][4];
        #pragma unroll
        for (int u = 0; u < 6; u++)
            #pragma unroll
            for (int q = 0; q < 4; q++) ga[u][q] = 0.f;
        #pragma unroll
        for (int kk = 0; kk < 4; kk++) {
            const uint32_t ch = (uint32_t)((kk * 16 + (lane >> 4) * 8) * 2);
            uint32_t ah[4], al[4], bh[3][4], bl[3][4];
            ldm4(su + SO_H1H + swz((uint32_t)((jb + (lane & 15)) * 128) + ch), ah);
            ldm4(su + SO_H1H + 16384u + swz((uint32_t)((jb + (lane & 15)) * 128) + ch), al);
            #pragma unroll
            for (int nb = 0; nb < 3; nb++) {
                const uint32_t off = swz((uint32_t)((nb * 16 + (lane & 15)) * 128) + ch);
                ldm4(su + SO_X0H + off, bh[nb]);
                ldm4(su + SO_X0H + 6144u + off, bl[nb]);
            }
            #pragma unroll
            for (int nb = 0; nb < 3; nb++)
                #pragma unroll
                for (int q = 0; q < 2; q++) {
                    float* c = ga[nb * 2 + q];
                    mmah(c, ah, bh[nb][q], bh[nb][q + 2]);
                    mmah(c, ah, bl[nb][q], bl[nb][q + 2]);
                    mmah(c, al, bh[nb][q], bh[nb][q + 2]);
                }
        }
        const int r0 = jb + (lane >> 2);
        #pragma unroll
        for (int nb = 0; nb < 3; nb++)
            #pragma unroll
            for (int q = 0; q < 2; q++) {
                const int i0 = nb * 16 + q * 8 + 2 * (lane & 3);
                const float* c = ga[nb * 2 + q];
                if (i0 < FIELD) {
                    g32[i0 * 128 + r0]     = c[0];
                    g32[i0 * 128 + r0 + 8] = c[2];
                }
                if (i0 + 1 < FIELD) {
                    g32[(i0 + 1) * 128 + r0]     = c[1];
                    g32[(i0 + 1) * 128 + r0 + 8] = c[3];
                }
            }
    }
    __syncthreads();
    // pack g -> fp16 hi/lo pairs
    uint32_t* gh2 = (uint32_t*)(smem + SO_X0T);
    uint32_t* gl2 = (uint32_t*)(smem + SO_X0H);
    for (int idx = tid; idx < 2496; idx += NTHR) {
        uint32_t lo;
        gh2[idx] = split2h2(g32[2 * idx], g32[2 * idx + 1], lo);
        gl2[idx] = lo;
    }
    __syncthreads();

    // ---- GEMV: out2[l] = sum_p W2h[p,l] * g[p], via HMMA n8 broadcast ----
    {
        auto stageg = [&](int st) {
            const int t0 = st * 4;
            const int n16 = (78 - t0 < 4 ? 78 - t0 : 4) * 512;
            const uint32_t dst = su + SO_A + (uint32_t)(st & 1) * 32768u;
            const char* src = (const char*)gA2 + (size_t)t0 * 8192;
            for (int idx = tid; idx < n16; idx += NTHR)
                cpasync16(dst + (uint32_t)idx * 16, src + idx * 16);
            CP_COMMIT();
        };
        const int tw = wid & 3, mb = wid >> 2;
        float gac[4] = {0.f, 0.f, 0.f, 0.f};
        stageg(0);
        for (int st = 0; st < 20; st++) {
            if (st + 1 < 20) { stageg(st + 1); CP_WAIT1(); }
            else CP_WAIT0();
            __syncthreads();
            const int gt = st * 4 + tw;
            if (gt < 78) {
                const uint32_t abase = su + SO_A + (uint32_t)(st & 1) * 32768u +
                                       (uint32_t)tw * 8192u;
                #pragma unroll
                for (int ks = 0; ks < 4; ks++) {
                    uint32_t a[4];
                    ldm4(abase + swz((uint32_t)((mb * 16 + (lane & 15)) * 128 +
                         (ks * 16 + (lane >> 4) * 8) * 2)), a);
                    const int gi = gt * 32 + ks * 8 + (lane & 3);
                    mmah(gac, a, gh2[gi], gh2[gi + 4]);
                    mmah(gac, a, gl2[gi], gl2[gi + 4]);
                }
            }
            __syncthreads();
        }
        if ((lane & 3) == 0) {
            gpart[wid * 16 + (lane >> 2)]     = gac[0];
            gpart[wid * 16 + (lane >> 2) + 8] = gac[2];
        }
    }
    __syncthreads();
    if (tid < 64) {
        const int mb = tid >> 4, r = tid & 15;
        const float s = gpart[(mb)      * 16 + r] + gpart[(mb + 4)  * 16 + r] +
                        gpart[(mb + 8)  * 16 + r] + gpart[(mb + 12) * 16 + r];
        outb[384 + tid] = s + 64.f * b2g[tid];
    }

    // ---- out[0..256) = sum_d h0T ----
    for (int l = tid; l < 256; l += NTHR) {
        float s = 0.f;
        #pragma unroll 8
        for (int d = 0; d < DIM; d++) s += h0T[d * HPH0 + l];
        outb[l] = s;
    }
}

extern "C" void kernel_launch(void* const* d_in, const int* in_sizes, int n_in,
                              void* d_out, int out_size) {
    const void*  feat = d_in[0];
    const float* emb  = (const float*)d_in[1];
    const float* W0   = (const float*)d_in[2];
    const float* b0   = (const float*)d_in[3];
    const float* W1   = (const float*)d_in[4];
    const float* b1   = (const float*)d_in[5];
    const float* W2   = (const float*)d_in[6];
    const float* b2   = (const float*)d_in[7];
    float* out = (float*)d_out;

    prep_kernel<<<282, 256>>>(W0, W1, W2);
    cudaFuncSetAttribute(cin_mma_kernel,
                         cudaFuncAttributeMaxDynamicSharedMemorySize, SMEM_BYTES);
    cin_mma_kernel<<<BATCH, NTHR, SMEM_BYTES>>>(feat, emb, b0, b1, b2, out);
}

// round 12
// speedup vs baseline: 1.0735x; 1.0735x over previous
#include <cuda_runtime.h>
#include <cuda_fp16.h>
#include <cstdint>

#define FIELD 39
#define DIM   64
#define NTHR  512
#define BATCH 2048

// SMEM layout (bytes)
#define HP0  40
#define HPH0 264
#define SO_X0T 0                       // fp32 x0T [d][i], stride 40 (10240)
#define SO_X0H 10240                   // fp16 x0 hi(6144)+lo(6144) [i<48][d]
#define SO_H0T 22528                   // fp32 h0T [d][j], stride 264 (67584)
#define SO_B   90112                   // B dbuf (64K); after L1: h1 hi/lo + g32
#define SO_A   155648                  // A dbuf / scratch / GEMV ring (64K)
#define SMEM_BYTES 221184

// Prepped W^T fp16 tile images (swizzle baked).
__device__ __align__(16) unsigned short gA0[48u  * 8192];  // 128x64 tiles
__device__ __align__(16) unsigned short gA1[156u * 8192];  // 128x64 tiles
__device__ __align__(16) unsigned short gA2[78u  * 4096];  // 64x64 tiles

__device__ __forceinline__ uint32_t swz(uint32_t off) {
    return off ^ ((off >> 3) & 0x70);
}
__device__ __forceinline__ void ldm4(uint32_t a, uint32_t r[4]) {
    asm volatile("ldmatrix.sync.aligned.m8n8.x4.shared.b16 {%0,%1,%2,%3}, [%4];"
                 : "=r"(r[0]), "=r"(r[1]), "=r"(r[2]), "=r"(r[3]) : "r"(a));
}
__device__ __forceinline__ void mmah(float c[4], const uint32_t a[4],
                                     uint32_t b0, uint32_t b1) {
    asm volatile("mma.sync.aligned.m16n8k16.row.col.f32.f16.f16.f32 "
                 "{%0,%1,%2,%3},{%4,%5,%6,%7},{%8,%9},{%0,%1,%2,%3};"
                 : "+f"(c[0]), "+f"(c[1]), "+f"(c[2]), "+f"(c[3])
                 : "r"(a[0]), "r"(a[1]), "r"(a[2]), "r"(a[3]), "r"(b0), "r"(b1));
}
__device__ __forceinline__ void cpasync16(uint32_t s, const void* g) {
    asm volatile("cp.async.cg.shared.global [%0], [%1], 16;" :: "r"(s), "l"(g));
}
#define CP_COMMIT() asm volatile("cp.async.commit_group;")
#define CP_WAIT0()  asm volatile("cp.async.wait_group 0;")
#define CP_WAIT1()  asm volatile("cp.async.wait_group 1;")

__device__ __forceinline__ unsigned short hbits(__half h) {
    return *(unsigned short*)&h;
}
__device__ __forceinline__ uint32_t pack2h(float a, float b) {
    return (uint32_t)hbits(__float2half_rn(a)) |
           ((uint32_t)hbits(__float2half_rn(b)) << 16);
}
// packed split: hi = f16x2(a,b), lo = f16x2 of residuals
__device__ __forceinline__ uint32_t split2h2(float a, float b, uint32_t& lo) {
    const __half2 h = __floats2half2_rn(a, b);
    const float2 hf = __half22float2(h);
    const __half2 l = __floats2half2_rn(a - hf.x, b - hf.y);
    lo = *(const uint32_t*)&l;
    return *(const uint32_t*)&h;
}

// ---- prep: W -> swizzle-baked fp16 W^T tile images ----
__global__ void prep_kernel(const float* __restrict__ W0,
                            const float* __restrict__ W1,
                            const float* __restrict__ W2) {
    const int tile = blockIdx.x;
    const float* W; unsigned short* A; int K, Lv, kt, mt, rows;
    if (tile < 48)       { kt = tile >> 1; mt = tile & 1; W = W0; K = 1521; Lv = 256;
                           rows = 128; A = gA0 + (size_t)tile * 8192; }
    else if (tile < 204) { int u = tile - 48;  kt = u; mt = 0; W = W1; K = 9984; Lv = 128;
                           rows = 128; A = gA1 + (size_t)u * 8192; }
    else                 { int u = tile - 204; kt = u; mt = 0; W = W2; K = 4992; Lv = 64;
                           rows = 64;  A = gA2 + (size_t)u * 4096; }
    for (int it = threadIdx.x; it < rows * 8; it += blockDim.x) {
        const int row = it % rows, cg = it / rows;
        const int l = mt * 128 + row;
        uint32_t hw[4];
        #pragma unroll
        for (int p = 0; p < 4; p++) {
            float v0 = 0.f, v1 = 0.f;
            const int k0 = kt * 64 + cg * 8 + 2 * p;
            if (l < Lv) {
                if (k0     < K) v0 = W[(size_t)k0 * Lv + l];
                if (k0 + 1 < K) v1 = W[(size_t)(k0 + 1) * Lv + l];
            }
            hw[p] = pack2h(v0, v1);
        }
        const uint32_t sw = swz((uint32_t)(row * 128 + cg * 16));
        *(uint4*)((char*)A + sw) = make_uint4(hw[0], hw[1], hw[2], hw[3]);
    }
}

// ---- build one 64-k B sub-chunk: B[d][k] = x0[i,d]*h[j,d], fp16 hi/lo ----
template<int FK, int HPREV>
__device__ __forceinline__ void build_b(char* smem, int t2, uint32_t bst,
                                        const float* __restrict__ hprevT) {
    const int tid = threadIdx.x;
    const float* x0T = (const float*)(smem + SO_X0T);
    const int d = tid >> 3, g = tid & 7;
    const int kb = t2 * 64 + g * 8;
    float v[8];
    if (FK == FIELD) {
        #pragma unroll
        for (int e = 0; e < 8; e++) {
            const int k = kb + e, i = k / FIELD, j = k - i * FIELD;
            v[e] = x0T[d * HP0 + i] * x0T[d * HP0 + j];
        }
    } else {
        const int i = kb / FK, j0 = kb % FK;
        const float xv = x0T[d * HP0 + i];
        const float4 a = *(const float4*)(hprevT + d * HPREV + j0);
        const float4 b = *(const float4*)(hprevT + d * HPREV + j0 + 4);
        v[0]=xv*a.x; v[1]=xv*a.y; v[2]=xv*a.z; v[3]=xv*a.w;
        v[4]=xv*b.x; v[5]=xv*b.y; v[6]=xv*b.z; v[7]=xv*b.w;
    }
    uint32_t hw[4], lw[4];
    #pragma unroll
    for (int p = 0; p < 4; p++) hw[p] = split2h2(v[2*p], v[2*p+1], lw[p]);
    const uint32_t sw = swz((uint32_t)(d * 128 + g * 16));
    char* bb = smem + SO_B + bst;
    *(uint4*)(bb + sw)        = make_uint4(hw[0], hw[1], hw[2], hw[3]);
    *(uint4*)(bb + 8192 + sw) = make_uint4(lw[0], lw[1], lw[2], lw[3]);
}

// ---- one 64-k sub-chunk of MMAs for this warp's 32x32 tile ----
// swz(r*128 + ch) = r*128 + (ch ^ ((r&7)<<4)) for ch < 128 — bases hoisted.
template<int L, int KKS>
__device__ __forceinline__ void chunk_mma(uint32_t su, uint32_t ast, uint32_t bst,
                                          int lrow, int dcol, int kk0,
                                          float acc[2][4][4]) {
    const int lane = threadIdx.x & 31;
    const uint32_t hi16 = (uint32_t)((lane >> 4) * 16);
    uint32_t abase[2], amask[2], bbase[2], bmask[2];
    #pragma unroll
    for (int mi = 0; mi < 2; mi++) {
        const int l = lrow + mi * 16 + (lane & 15);
        const int mt = (L == 256) ? (l >> 7) : 0;
        const int r  = (L == 256) ? (l & 127) : l;
        abase[mi] = su + SO_A + ast + (uint32_t)mt * 16384u + (uint32_t)r * 128u;
        amask[mi] = (uint32_t)((r & 7) << 4);
    }
    #pragma unroll
    for (int nb = 0; nb < 2; nb++) {
        const int d = dcol + nb * 16 + (lane & 15);
        bbase[nb] = su + SO_B + bst + (uint32_t)d * 128u;
        bmask[nb] = (uint32_t)((d & 7) << 4);
    }
    #pragma unroll
    for (int u = 0; u < KKS; u++) {
        const uint32_t ch = (uint32_t)((kk0 + u) * 32) + hi16;
        uint32_t ah[2][4], bh[2][4], bl[2][4];
        #pragma unroll
        for (int nb = 0; nb < 2; nb++) {
            const uint32_t ba = bbase[nb] + (ch ^ bmask[nb]);
            ldm4(ba, bh[nb]);
            ldm4(ba + 8192u, bl[nb]);
        }
        #pragma unroll
        for (int mi = 0; mi < 2; mi++)
            ldm4(abase[mi] + (ch ^ amask[mi]), ah[mi]);
        #pragma unroll
        for (int mi = 0; mi < 2; mi++)
            #pragma unroll
            for (int j = 0; j < 4; j++) {
                const int nb = j >> 1, q = j & 1;
                mmah(acc[mi][j], ah[mi], bh[nb][q], bh[nb][q + 2]);
                mmah(acc[mi][j], ah[mi], bl[nb][q], bl[nb][q + 2]);
            }
    }
}

// ---- one CIN layer. SUB 64-k sub-chunks per barrier.
// EPI=0: fp32 [d][l] store to houtT. EPI=1: fp16 h1 hi/lo into B region + rowsums.
template<int L, int FK, int NKT, int SUB, int S, int HPREV, int HPOUT, int EPI>
__device__ void run_layer(char* smem, uint32_t su, const unsigned short* gA,
                          const float* __restrict__ hprevT, float* houtT,
                          const float* __restrict__ biasg, float* outAcc) {
    const int tid = threadIdx.x, wid = tid >> 5, lane = tid & 31;
    constexpr int NTL = L / 32, NTILES = NTL * 2;
    constexpr int KKS = 4 / S;
    constexpr uint32_t ASTB = (uint32_t)SUB * (uint32_t)L * 128u;  // 32K both
    constexpr uint32_t BSTG = (uint32_t)SUB * 16384u;
    const int tile = wid % NTILES, slice = wid / NTILES;
    const int lrow = (tile % NTL) * 32, dcol = (tile / NTL) * 32;
    const int kk0 = slice * KKS;

    float acc[2][4][4];
    #pragma unroll
    for (int mi = 0; mi < 2; mi++)
        #pragma unroll
        for (int j = 0; j < 4; j++)
            #pragma unroll
            for (int q = 0; q < 4; q++) acc[mi][j][q] = 0.f;

    auto stage_a = [&](int t) {
        const uint32_t dst = su + SO_A + (uint32_t)(t & 1) * 32768u;
        const char* src = (const char*)gA + (size_t)t * ASTB;
        constexpr int N16 = (int)(ASTB / 16);
        for (int idx = tid; idx < N16; idx += NTHR)
            cpasync16(dst + (uint32_t)idx * 16, src + idx * 16);
        CP_COMMIT();
    };
    auto build_chunk = [&](int t) {
        #pragma unroll
        for (int sub = 0; sub < SUB; sub++)
            build_b<FK, HPREV>(smem, t * SUB + sub,
                               (uint32_t)(t & 1) * BSTG + (uint32_t)sub * 16384u,
                               hprevT);
    };

    stage_a(0);
    build_chunk(0);
    CP_WAIT0();
    __syncthreads();

    for (int t = 0; t < NKT; t++) {
        const bool more = (t + 1 < NKT);
        if (more) stage_a(t + 1);
        #pragma unroll
        for (int sub = 0; sub < SUB; sub++)
            chunk_mma<L, KKS>(su,
                (uint32_t)(t & 1) * 32768u + (SUB == 2 ? (uint32_t)sub * 16384u : 0u),
                (uint32_t)(t & 1) * BSTG + (uint32_t)sub * 16384u,
                lrow, dcol, kk0, acc);
        if (more) build_chunk(t + 1);
        CP_WAIT0();
        __syncthreads();
    }

    // ---- k-slice reduction through A region (dead now) ----
    if (S > 1) {
        if (slice != 0) {
            float4* dst = (float4*)(smem + SO_A +
                (size_t)(((slice - 1) * NTILES + tile) * 4096 + lane * 128));
            #pragma unroll
            for (int mi = 0; mi < 2; mi++)
                #pragma unroll
                for (int j = 0; j < 4; j++)
                    dst[mi * 4 + j] = *(float4*)acc[mi][j];
        }
        __syncthreads();
        if (slice == 0) {
            #pragma unroll
            for (int s = 1; s < S; s++) {
                const float4* src = (const float4*)(smem + SO_A +
                    (size_t)(((s - 1) * NTILES + tile) * 4096 + lane * 128));
                #pragma unroll
                for (int mi = 0; mi < 2; mi++)
                    #pragma unroll
                    for (int j = 0; j < 4; j++) {
                        const float4 v = src[mi * 4 + j];
                        acc[mi][j][0] += v.x; acc[mi][j][1] += v.y;
                        acc[mi][j][2] += v.z; acc[mi][j][3] += v.w;
                    }
            }
        }
        __syncthreads();   // B region reuse (h1h) must wait for all reads
    }

    if (slice == 0) {
        const int g = lane >> 2, t4 = lane & 3;
        if (EPI == 0) {
            #pragma unroll
            for (int mi = 0; mi < 2; mi++) {
                const int la = lrow + mi * 16 + g;
                const float b0 = biasg[la], b1 = biasg[la + 8];
                #pragma unroll
                for (int j = 0; j < 4; j++) {
                    const int db = dcol + (j >> 1) * 16 + (j & 1) * 8 + 2 * t4;
                    houtT[db * HPOUT + la]           = acc[mi][j][0] + b0;
                    houtT[(db + 1) * HPOUT + la]     = acc[mi][j][1] + b0;
                    houtT[db * HPOUT + la + 8]       = acc[mi][j][2] + b1;
                    houtT[(db + 1) * HPOUT + la + 8] = acc[mi][j][3] + b1;
                }
            }
        } else {
            // h1 hi/lo into B region ([j<128][d] swizzled rows) + rowsums
            #pragma unroll
            for (int mi = 0; mi < 2; mi++) {
                const int la = lrow + mi * 16 + g;
                const float b0 = biasg[la], b1 = biasg[la + 8];
                float s0 = 0.f, s1 = 0.f;
                #pragma unroll
                for (int j = 0; j < 4; j++) {
                    const int db = dcol + (j >> 1) * 16 + (j & 1) * 8 + 2 * t4;
                    uint32_t lo, hi;
                    hi = split2h2(acc[mi][j][0] + b0, acc[mi][j][1] + b0, lo);
                    *(uint32_t*)(smem + SO_B + swz((uint32_t)(la * 128 + db * 2))) = hi;
                    *(uint32_t*)(smem + SO_B + 16384u + swz((uint32_t)(la * 128 + db * 2))) = lo;
                    hi = split2h2(acc[mi][j][2] + b1, acc[mi][j][3] + b1, lo);
                    *(uint32_t*)(smem + SO_B + swz((uint32_t)((la + 8) * 128 + db * 2))) = hi;
                    *(uint32_t*)(smem + SO_B + 16384u + swz((uint32_t)((la + 8) * 128 + db * 2))) = lo;
                    s0 += acc[mi][j][0] + acc[mi][j][1];
                    s1 += acc[mi][j][2] + acc[mi][j][3];
                }
                s0 += __shfl_xor_sync(0xffffffffu, s0, 1);
                s0 += __shfl_xor_sync(0xffffffffu, s0, 2);
                s1 += __shfl_xor_sync(0xffffffffu, s1, 1);
                s1 += __shfl_xor_sync(0xffffffffu, s1, 2);
                if (t4 == 0) {
                    outAcc[(dcol >> 5) * 128 + la]     = s0;
                    outAcc[(dcol >> 5) * 128 + la + 8] = s1;
                }
            }
        }
    }
    __syncthreads();
}

__global__ void __launch_bounds__(NTHR, 1)
cin_mma_kernel(const void* __restrict__ feat_ids_raw,
               const float* __restrict__ emb,
               const float* __restrict__ b0g, const float* __restrict__ b1g,
               const float* __restrict__ b2g, float* __restrict__ out) {
    extern __shared__ char smem[];
    const uint32_t su = (uint32_t)__cvta_generic_to_shared(smem);
    const int b = blockIdx.x, tid = threadIdx.x, wid = tid >> 5, lane = tid & 31;
    float* x0T = (float*)(smem + SO_X0T);
    float* h0T = (float*)(smem + SO_H0T);
    __shared__ long long sids[FIELD];
    __shared__ int is64flag;
    __shared__ float outAcc[2 * 128];
    __shared__ float gpart[256];

    if (tid == 0) {
        const unsigned int* w = (const unsigned int*)feat_ids_raw;
        int f = 1;
        #pragma unroll
        for (int t = 0; t < 32; t++) if (w[2*t+1] != 0u) { f = 0; break; }
        is64flag = f;
    }
    __syncthreads();
    if (tid < FIELD) {
        sids[tid] = is64flag
            ? ((const long long*)feat_ids_raw)[(size_t)b * FIELD + tid]
            : (long long)((const int*)feat_ids_raw)[(size_t)b * FIELD + tid];
    }
    __syncthreads();
    for (int t = tid; t < FIELD * DIM; t += NTHR) {
        const int i = t >> 6, d = t & 63;
        x0T[d * HP0 + i] = emb[(size_t)sids[i] * DIM + d];
    }
    if (tid < 64) x0T[tid * HP0 + FIELD] = 0.f;   // zero pad col (K padding)
    __syncthreads();
    // x0h: fp16 hi/lo [i<48][d] swizzled rows (pairs of adjacent d)
    for (int e = tid; e < 48 * 32; e += NTHR) {
        const int i = e >> 5, dp = (e & 31) * 2;
        float v0 = 0.f, v1 = 0.f;
        if (i < FIELD) { v0 = x0T[dp * HP0 + i]; v1 = x0T[(dp + 1) * HP0 + i]; }
        uint32_t lo;
        const uint32_t hi = split2h2(v0, v1, lo);
        const uint32_t off = swz((uint32_t)(i * 128 + dp * 2));
        *(uint32_t*)(smem + SO_X0H + off) = hi;
        *(uint32_t*)(smem + SO_X0H + 6144u + off) = lo;
    }
    __syncthreads();

    run_layer<256,  39, 24, 1, 1, HP0,  HPH0, 0>(smem, su, gA0, x0T, h0T, b0g, outAcc);
    run_layer<128, 256, 78, 2, 2, HPH0,    0, 1>(smem, su, gA1, h0T, (float*)0, b1g, outAcc);

    float* outb = out + (size_t)b * 448;
    if (tid < 128)
        outb[256 + tid] = outAcc[tid] + outAcc[128 + tid] + 64.f * b1g[tid];

    // ---- G = H1 (128xK64) x X0^T (48) : 3-product fp16 GEMM ----
    // h1 hi at SO_B, lo at SO_B+16384; g32 at SO_B+32768.
    float* g32 = (float*)(smem + SO_B + 32768);
    if (wid < 8) {
        const int jb = wid * 16;
        float ga[6][4];
        #pragma unroll
        for (int u = 0; u < 6; u++)
            #pragma unroll
            for (int q = 0; q < 4; q++) ga[u][q] = 0.f;
        #pragma unroll
        for (int kk = 0; kk < 4; kk++) {
            const uint32_t ch = (uint32_t)((kk * 16 + (lane >> 4) * 8) * 2);
            uint32_t ah[4], al[4], bh[3][4], bl[3][4];
            ldm4(su + SO_B + swz((uint32_t)((jb + (lane & 15)) * 128) + ch), ah);
            ldm4(su + SO_B + 16384u + swz((uint32_t)((jb + (lane & 15)) * 128) + ch), al);
            #pragma unroll
            for (int nb = 0; nb < 3; nb++) {
                const uint32_t off = swz((uint32_t)((nb * 16 + (lane & 15)) * 128) + ch);
                ldm4(su + SO_X0H + off, bh[nb]);
                ldm4(su + SO_X0H + 6144u + off, bl[nb]);
            }
            #pragma unroll
            for (int nb = 0; nb < 3; nb++)
                #pragma unroll
                for (int q = 0; q < 2; q++) {
                    float* c = ga[nb * 2 + q];
                    mmah(c, ah, bh[nb][q], bh[nb][q + 2]);
                    mmah(c, ah, bl[nb][q], bl[nb][q + 2]);
                    mmah(c, al, bh[nb][q], bh[nb][q + 2]);
                }
        }
        const int r0 = jb + (lane >> 2);
        #pragma unroll
        for (int nb = 0; nb < 3; nb++)
            #pragma unroll
            for (int q = 0; q < 2; q++) {
                const int i0 = nb * 16 + q * 8 + 2 * (lane & 3);
                const float* c = ga[nb * 2 + q];
                if (i0 < FIELD) {
                    g32[i0 * 128 + r0]     = c[0];
                    g32[i0 * 128 + r0 + 8] = c[2];
                }
                if (i0 + 1 < FIELD) {
                    g32[(i0 + 1) * 128 + r0]     = c[1];
                    g32[(i0 + 1) * 128 + r0 + 8] = c[3];
                }
            }
    }
    __syncthreads();
    // pack g -> fp16 hi/lo pairs
    uint32_t* gh2 = (uint32_t*)(smem + SO_X0T);
    uint32_t* gl2 = (uint32_t*)(smem + SO_X0H);
    for (int idx = tid; idx < 2496; idx += NTHR) {
        uint32_t lo;
        gh2[idx] = split2h2(g32[2 * idx], g32[2 * idx + 1], lo);
        gl2[idx] = lo;
    }
    __syncthreads();

    // ---- GEMV: out2[l] = sum_p W2h[p,l] * g[p], via HMMA n8 broadcast ----
    {
        auto stageg = [&](int st) {
            const int t0 = st * 4;
            const int n16 = (78 - t0 < 4 ? 78 - t0 : 4) * 512;
            const uint32_t dst = su + SO_A + (uint32_t)(st & 1) * 32768u;
            const char* src = (const char*)gA2 + (size_t)t0 * 8192;
            for (int idx = tid; idx < n16; idx += NTHR)
                cpasync16(dst + (uint32_t)idx * 16, src + idx * 16);
            CP_COMMIT();
        };
        const int tw = wid & 3, mb = wid >> 2;
        float gac[4] = {0.f, 0.f, 0.f, 0.f};
        stageg(0);
        for (int st = 0; st < 20; st++) {
            if (st + 1 < 20) { stageg(st + 1); CP_WAIT1(); }
            else CP_WAIT0();
            __syncthreads();
            const int gt = st * 4 + tw;
            if (gt < 78) {
                const uint32_t abase = su + SO_A + (uint32_t)(st & 1) * 32768u +
                                       (uint32_t)tw * 8192u;
                #pragma unroll
                for (int ks = 0; ks < 4; ks++) {
                    uint32_t a[4];
                    ldm4(abase + swz((uint32_t)((mb * 16 + (lane & 15)) * 128 +
                         (ks * 16 + (lane >> 4) * 8) * 2)), a);
                    const int gi = gt * 32 + ks * 8 + (lane & 3);
                    mmah(gac, a, gh2[gi], gh2[gi + 4]);
                    mmah(gac, a, gl2[gi], gl2[gi + 4]);
                }
            }
            __syncthreads();
        }
        if ((lane & 3) == 0) {
            gpart[wid * 16 + (lane >> 2)]     = gac[0];
            gpart[wid * 16 + (lane >> 2) + 8] = gac[2];
        }
    }
    __syncthreads();
    if (tid < 64) {
        const int mb = tid >> 4, r = tid & 15;
        const float s = gpart[(mb)      * 16 + r] + gpart[(mb + 4)  * 16 + r] +
                        gpart[(mb + 8)  * 16 + r] + gpart[(mb + 12) * 16 + r];
        outb[384 + tid] = s + 64.f * b2g[tid];
    }

    // ---- out[0..256) = sum_d h0T ----
    for (int l = tid; l < 256; l += NTHR) {
        float s = 0.f;
        #pragma unroll 8
        for (int d = 0; d < DIM; d++) s += h0T[d * HPH0 + l];
        outb[l] = s;
    }
}

extern "C" void kernel_launch(void* const* d_in, const int* in_sizes, int n_in,
                              void* d_out, int out_size) {
    const void*  feat = d_in[0];
    const float* emb  = (const float*)d_in[1];
    const float* W0   = (const float*)d_in[2];
    const float* b0   = (const float*)d_in[3];
    const float* W1   = (const float*)d_in[4];
    const float* b1   = (const float*)d_in[5];
    const float* W2   = (const float*)d_in[6];
    const float* b2   = (const float*)d_in[7];
    float* out = (float*)d_out;

    prep_kernel<<<282, 256>>>(W0, W1, W2);
    cudaFuncSetAttribute(cin_mma_kernel,
                         cudaFuncAttributeMaxDynamicSharedMemorySize, SMEM_BYTES);
    cin_mma_kernel<<<BATCH, NTHR, SMEM_BYTES>>>(feat, emb, b0, b1, b2, out);
}